// round 8
// baseline (speedup 1.0000x reference)
#include <cuda_runtime.h>

#define INV_CELL 20.0f
#define PTS 16           // points per block
#define NTHREADS 128     // 8 threads per point
#define GR_STRIDE 49     // float4 per grad row (48 + 1 pad)

// Cubic B-spline basis + gradient for a single stencil offset m (0..3).
// x = f + 1 - m deterministically falls in branch: m=0 -> [1,2), m=1 -> [0,1),
// m=2 -> [-1,0), m=3 -> [-2,-1). Coefficient sets selected at compile time;
// FMA chains identical in shape to the reference polynomials.
__device__ __forceinline__ void spline1(float f, int m, float& b, float& db) {
    float x  = f + (float)(1 - m);
    float a3 = (m == 0) ? -1.0f/6.0f : (m == 1) ? 0.5f : (m == 2) ? -0.5f : 1.0f/6.0f;
    float a2 = (m == 0 || m == 3) ? 1.0f : -1.0f;
    float a1 = (m == 0) ? -2.0f : (m == 3) ? 2.0f : 0.0f;
    float a0 = (m == 0 || m == 3) ? 4.0f/3.0f : 2.0f/3.0f;
    float d2 = (m == 0) ? -0.5f : (m == 1) ? 1.5f : (m == 2) ? -1.5f : 0.5f;
    float d1 = (m == 0 || m == 3) ? 2.0f : -2.0f;
    float d0 = (m == 0) ? -2.0f : (m == 3) ? 2.0f : 0.0f;
    b  = ((a3 * x + a2) * x + a1) * x + a0;
    db = INV_CELL * ((d2 * x + d1) * x + d0);
}

// Basis only (for the direct sf stores).
__device__ __forceinline__ float basis1(float f, int m) {
    float x  = f + (float)(1 - m);
    float a3 = (m == 0) ? -1.0f/6.0f : (m == 1) ? 0.5f : (m == 2) ? -0.5f : 1.0f/6.0f;
    float a2 = (m == 0 || m == 3) ? 1.0f : -1.0f;
    float a1 = (m == 0) ? -2.0f : (m == 3) ? 2.0f : 0.0f;
    float a0 = (m == 0 || m == 3) ? 4.0f/3.0f : 2.0f/3.0f;
    return ((a3 * x + a2) * x + a1) * x + a0;
}

__global__ void __launch_bounds__(NTHREADS, 12)
cubic_shape_kernel(const float* __restrict__ pos,
                   float* __restrict__ out_sf,
                   float* __restrict__ out_grad,
                   int n_points) {
    __shared__ float4 gr_s[PTS * GR_STRIDE];   // 12544 B

    int tid = threadIdx.x;
    int g   = tid >> 3;        // local point 0..15
    int s   = tid & 7;
    int i   = s >> 1;          // x-stencil index owned for grad
    int jh  = s & 1;           // y half for grad: j in {2jh, 2jh+1}
    int n   = blockIdx.x * PTS + g;

    if (n < n_points) {
        float px = __ldg(&pos[n * 3 + 0]);
        float py = __ldg(&pos[n * 3 + 1]);
        float pz = __ldg(&pos[n * 3 + 2]);

        float rx = px * INV_CELL, ry = py * INV_CELL, rz = pz * INV_CELL;
        float fx = rx - floorf(rx);
        float fy = ry - floorf(ry);
        float fz = rz - floorf(rz);

        // z: all 4 offsets
        float bz[4], dbz[4];
#pragma unroll
        for (int m = 0; m < 4; m++) spline1(fz, m, bz[m], dbz[m]);

        // ---- sf: direct, perfectly coalesced stores ----
        // Thread s owns sf float4 indices {s, s+8}:  q = 4*iq + jq
        //   q1 = s     -> iq = s>>2,       jq = s&3
        //   q2 = s + 8 -> iq = (s>>2) + 2, jq = s&3
        // Per warp (4 points) each store touches exactly 4 aligned 128B lines.
        {
            int   iq  = s >> 2;
            int   jq  = s & 3;
            float bxa = basis1(fx, iq);        // compile-time coefs after unroll? iq runtime:
            float bxb = basis1(fx, iq + 2);    // SEL-selected coefs (iq in {0,1}) — cheap
            float byq = basis1(fy, jq);
            float va  = bxa * byq;
            float vb  = bxb * byq;
            float4* sfp = reinterpret_cast<float4*>(out_sf) + (size_t)n * 16;
            __stcs(&sfp[s],     make_float4(va * bz[0], va * bz[1], va * bz[2], va * bz[3]));
            __stcs(&sfp[s + 8], make_float4(vb * bz[0], vb * bz[1], vb * bz[2], vb * bz[3]));
        }

        // ---- grad: stage in smem ----
        float bxi, dbxi;  spline1(fx, i, bxi, dbxi);
        float by0, dby0;  spline1(fy, 2 * jh,     by0, dby0);
        float by1, dby1;  spline1(fy, 2 * jh + 1, by1, dby1);

#pragma unroll
        for (int t = 0; t < 2; t++) {
            int   j   = 2 * jh + t;
            float bj  = t ? by1  : by0;
            float dbj = t ? dby1 : dby0;
            float bij    = bxi * bj;
            float dbi_bj = dbxi * bj;
            float bi_dbj = bxi * dbj;

            float gg[12];
#pragma unroll
            for (int k = 0; k < 4; k++) {
                gg[k * 3 + 0] = dbi_bj * bz[k];
                gg[k * 3 + 1] = bi_dbj * bz[k];
                gg[k * 3 + 2] = bij * dbz[k];
            }
            int base = g * GR_STRIDE + i * 12 + j * 3;
            gr_s[base + 0] = make_float4(gg[0], gg[1], gg[2],  gg[3]);
            gr_s[base + 1] = make_float4(gg[4], gg[5], gg[6],  gg[7]);
            gr_s[base + 2] = make_float4(gg[8], gg[9], gg[10], gg[11]);
        }
    }
    __syncthreads();

    // ---- grad copy-out: perfectly coalesced float4 streaming stores ----
    // PTS*48 = 768 float4 per block; smem addr = idx + idx/48 (stride 49)
    {
        int   blk_base = blockIdx.x * (PTS * 48);
        int   total    = n_points * 48;
        float4* dst    = reinterpret_cast<float4*>(out_grad);
#pragma unroll
        for (int p = 0; p < 6; p++) {
            int idx  = p * NTHREADS + tid;        // 0..767
            int gidx = blk_base + idx;
            if (gidx < total) {
                __stcs(&dst[gidx], gr_s[idx + idx / 48]);
            }
        }
    }
}

extern "C" void kernel_launch(void* const* d_in, const int* in_sizes, int n_in,
                              void* d_out, int out_size) {
    const float* pos = (const float*)d_in[0];
    int n_points = in_sizes[0] / 3;

    float* out_sf   = (float*)d_out;                      // [N, 64]
    float* out_grad = out_sf + (size_t)n_points * 64;     // [N, 64, 3]

    int grid = (n_points + PTS - 1) / PTS;
    cubic_shape_kernel<<<grid, NTHREADS>>>(pos, out_sf, out_grad, n_points);
}

// round 9
// speedup vs baseline: 1.0098x; 1.0098x over previous
#include <cuda_runtime.h>

#define INV_CELL 20.0f
#define NTHREADS 128     // 4 warps; each warp owns 4 points
#define PTS 16           // points per block
#define WPTS 4           // points per warp
#define GR_STRIDE 49     // float4 per grad point-row (48 + 1 pad)
#define WARP_CHUNK (WPTS * GR_STRIDE)   // 196 float4 per warp

// Cubic B-spline basis + gradient for a single stencil offset m (0..3).
// x = f + 1 - m deterministically falls in branch: m=0 -> [1,2), m=1 -> [0,1),
// m=2 -> [-1,0), m=3 -> [-2,-1). Coefficient sets selected branch-free;
// FMA chains identical in shape to the reference polynomials.
__device__ __forceinline__ void spline1(float f, int m, float& b, float& db) {
    float x  = f + (float)(1 - m);
    float a3 = (m == 0) ? -1.0f/6.0f : (m == 1) ? 0.5f : (m == 2) ? -0.5f : 1.0f/6.0f;
    float a2 = (m == 0 || m == 3) ? 1.0f : -1.0f;
    float a1 = (m == 0) ? -2.0f : (m == 3) ? 2.0f : 0.0f;
    float a0 = (m == 0 || m == 3) ? 4.0f/3.0f : 2.0f/3.0f;
    float d2 = (m == 0) ? -0.5f : (m == 1) ? 1.5f : (m == 2) ? -1.5f : 0.5f;
    float d1 = (m == 0 || m == 3) ? 2.0f : -2.0f;
    float d0 = (m == 0) ? -2.0f : (m == 3) ? 2.0f : 0.0f;
    b  = ((a3 * x + a2) * x + a1) * x + a0;
    db = INV_CELL * ((d2 * x + d1) * x + d0);
}

// Basis only (for the direct sf stores).
__device__ __forceinline__ float basis1(float f, int m) {
    float x  = f + (float)(1 - m);
    float a3 = (m == 0) ? -1.0f/6.0f : (m == 1) ? 0.5f : (m == 2) ? -0.5f : 1.0f/6.0f;
    float a2 = (m == 0 || m == 3) ? 1.0f : -1.0f;
    float a1 = (m == 0) ? -2.0f : (m == 3) ? 2.0f : 0.0f;
    float a0 = (m == 0 || m == 3) ? 4.0f/3.0f : 2.0f/3.0f;
    return ((a3 * x + a2) * x + a1) * x + a0;
}

__global__ void __launch_bounds__(NTHREADS, 12)
cubic_shape_kernel(const float* __restrict__ pos,
                   float* __restrict__ out_sf,
                   float* __restrict__ out_grad,
                   int n_points) {
    __shared__ float4 gr_s[4 * WARP_CHUNK];   // 12544 B, one chunk per warp

    int tid  = threadIdx.x;
    int w    = tid >> 5;       // warp id 0..3
    int lane = tid & 31;
    int gl   = lane >> 3;      // local point within warp 0..3
    int s    = lane & 7;
    int i    = s >> 1;         // x-stencil index owned for grad
    int jh   = s & 1;          // y half for grad
    int wpt0 = blockIdx.x * PTS + w * WPTS;   // first point of this warp
    int n    = wpt0 + gl;

    float4* warp_s = gr_s + w * WARP_CHUNK;

    if (n < n_points) {
        float px = __ldg(&pos[n * 3 + 0]);
        float py = __ldg(&pos[n * 3 + 1]);
        float pz = __ldg(&pos[n * 3 + 2]);

        float rx = px * INV_CELL, ry = py * INV_CELL, rz = pz * INV_CELL;
        float fx = rx - floorf(rx);
        float fy = ry - floorf(ry);
        float fz = rz - floorf(rz);

        // z: all 4 offsets
        float bz[4], dbz[4];
#pragma unroll
        for (int m = 0; m < 4; m++) spline1(fz, m, bz[m], dbz[m]);

        // ---- grad: stage in this warp's smem chunk ----
        float bxi, dbxi;  spline1(fx, i, bxi, dbxi);
        float by0, dby0;  spline1(fy, 2 * jh,     by0, dby0);
        float by1, dby1;  spline1(fy, 2 * jh + 1, by1, dby1);

#pragma unroll
        for (int t = 0; t < 2; t++) {
            int   j   = 2 * jh + t;
            float bj  = t ? by1  : by0;
            float dbj = t ? dby1 : dby0;
            float bij    = bxi * bj;
            float dbi_bj = dbxi * bj;
            float bi_dbj = bxi * dbj;

            float gg[12];
#pragma unroll
            for (int k = 0; k < 4; k++) {
                gg[k * 3 + 0] = dbi_bj * bz[k];
                gg[k * 3 + 1] = bi_dbj * bz[k];
                gg[k * 3 + 2] = bij * dbz[k];
            }
            int base = gl * GR_STRIDE + i * 12 + j * 3;
            warp_s[base + 0] = make_float4(gg[0], gg[1], gg[2],  gg[3]);
            warp_s[base + 1] = make_float4(gg[4], gg[5], gg[6],  gg[7]);
            warp_s[base + 2] = make_float4(gg[8], gg[9], gg[10], gg[11]);
        }

        // ---- sf: direct, perfectly coalesced stores (while STS drains) ----
        // Thread s owns sf float4 indices {s, s+8} of its point.
        {
            int   iq  = s >> 2;
            int   jq  = s & 3;
            float bxa = basis1(fx, iq);
            float bxb = basis1(fx, iq + 2);
            float byq = basis1(fy, jq);
            float va  = bxa * byq;
            float vb  = bxb * byq;
            float4* sfp = reinterpret_cast<float4*>(out_sf) + (size_t)n * 16;
            __stcs(&sfp[s],     make_float4(va * bz[0], va * bz[1], va * bz[2], va * bz[3]));
            __stcs(&sfp[s + 8], make_float4(vb * bz[0], vb * bz[1], vb * bz[2], vb * bz[3]));
        }
    }
    __syncwarp();

    // ---- grad copy-out: warp-local, perfectly coalesced float4 streams ----
    // Warp covers flat float4 range [wpt0*48, wpt0*48 + 192).
    {
        int   wbase = wpt0 * 48;
        int   total = n_points * 48;
        float4* dst = reinterpret_cast<float4*>(out_grad);
        if (wbase + 192 <= total) {
#pragma unroll
            for (int p = 0; p < 6; p++) {
                int idx = p * 32 + lane;           // 0..191
                __stcs(&dst[wbase + idx], warp_s[idx + idx / 48]);
            }
        } else {
#pragma unroll
            for (int p = 0; p < 6; p++) {
                int idx = p * 32 + lane;
                if (wbase + idx < total)
                    __stcs(&dst[wbase + idx], warp_s[idx + idx / 48]);
            }
        }
    }
}

extern "C" void kernel_launch(void* const* d_in, const int* in_sizes, int n_in,
                              void* d_out, int out_size) {
    const float* pos = (const float*)d_in[0];
    int n_points = in_sizes[0] / 3;

    float* out_sf   = (float*)d_out;                      // [N, 64]
    float* out_grad = out_sf + (size_t)n_points * 64;     // [N, 64, 3]

    int grid = (n_points + PTS - 1) / PTS;
    cubic_shape_kernel<<<grid, NTHREADS>>>(pos, out_sf, out_grad, n_points);
}